// round 2
// baseline (speedup 1.0000x reference)
#include <cuda_runtime.h>

// Conv4d: x(2,8,16,40,40,40) * W(3,32,8,3,3,3) + bias(3,32) -> out(2,32,16,40,40,40)
// f32x2-packed direct conv. Thread tile: 8 co (4 pairs) x 8 w. Block: 80 threads,
// spatial tile 4d x 4h x 40w at fixed (b, t, co-group-of-8).

typedef unsigned long long u64;

__device__ __forceinline__ u64 pack2(float lo, float hi) {
    u64 r; asm("mov.b64 %0, {%1, %2};" : "=l"(r) : "f"(lo), "f"(hi)); return r;
}
__device__ __forceinline__ void unpack2(float& lo, float& hi, u64 v) {
    asm("mov.b64 {%0, %1}, %2;" : "=f"(lo), "=f"(hi) : "l"(v));
}
__device__ __forceinline__ u64 ffma2(u64 a, u64 b, u64 c) {
    u64 d; asm("fma.rn.f32x2 %0, %1, %2, %3;" : "=l"(d) : "l"(a), "l"(b), "l"(c)); return d;
}

#define NT 80

__global__ void __launch_bounds__(NT) conv4d_kernel(
    const float* __restrict__ x, const float* __restrict__ weight,
    const float* __restrict__ bias, float* __restrict__ out)
{
    __shared__ float sx[4 * 6 * 6 * 44];   // [ci4][dd6][hh6][ww44], 6336 f, halo zero-filled once
    __shared__ float sw[3 * 8 * 27 * 8];   // [kt][ci8][kd][kh][kw][co8], 5184 f

    const int tid = threadIdx.x;
    const int wg  = tid % 5;            // w0 = wg*8
    const int hl  = (tid / 5) % 4;
    const int dl  = tid / 20;
    const int w0  = wg * 8;

    const int bx  = blockIdx.x;         // 0..99 -> (d0,h0)
    const int cog = blockIdx.y;         // 0..3
    const int bz  = blockIdx.z;         // 0..31 -> (b,t)
    const int d0  = (bx % 10) * 4;
    const int h0  = (bx / 10) * 4;
    const int b   = bz >> 4;
    const int t   = bz & 15;

    // --- one-time: zero x slab (halo / always-invalid cells rely on this) ---
    for (int idx = tid; idx < 4 * 6 * 6 * 44; idx += NT) sx[idx] = 0.f;

    // --- one-time: stage ALL weights, layout [kt][ci8][kd][kh][kw][co8] ---
    for (int idx = tid; idx < 5184; idx += NT) {
        int co = idx & 7;
        int r  = idx >> 3;
        int kw = r % 3; r /= 3;
        int kh = r % 3; r /= 3;
        int kd = r % 3; r /= 3;
        int ci = r & 7;
        int kt = r >> 3;
        sw[idx] = weight[(kt * 32 + cog * 8 + co) * 216 + ci * 27 + kd * 9 + kh * 3 + kw];
    }

    // --- accumulators: 4 co-pairs x 8 w, init with effective bias ---
    u64 acc[4][8];
    #pragma unroll
    for (int cp = 0; cp < 4; ++cp) {
        float s0 = 0.f, s1 = 0.f;
        #pragma unroll
        for (int kt = 0; kt < 3; ++kt) {
            int tf = t + kt - 1;
            if (tf >= 0 && tf < 16) {
                s0 += bias[kt * 32 + cog * 8 + cp * 2];
                s1 += bias[kt * 32 + cog * 8 + cp * 2 + 1];
            }
        }
        u64 sv = pack2(s0, s1);
        #pragma unroll
        for (int wi = 0; wi < 8; ++wi) acc[cp][wi] = sv;
    }

    for (int kt = 0; kt < 3; ++kt) {
        const int tf = t + kt - 1;
        if (tf < 0 || tf >= 16) continue;              // uniform across block
        const float* xg = x + b * 8192000 + tf * 64000;

        for (int cib = 0; cib < 2; ++cib) {
            __syncthreads();
            // stage valid interior: 4 ci x 6 dd x 6 hh x 40 ww
            for (int idx = tid; idx < 5760; idx += NT) {
                int ci = idx / 1440;
                int r  = idx - ci * 1440;
                int dd = r / 240;
                int r2 = r - dd * 240;
                int hh = r2 / 40;
                int ww = r2 - hh * 40;               // global w = ww, smem col = ww+1
                int gd = d0 + dd - 1, gh = h0 + hh - 1;
                if ((unsigned)gd < 40u && (unsigned)gh < 40u)
                    sx[((ci * 6 + dd) * 6 + hh) * 44 + ww + 1] =
                        xg[(cib * 4 + ci) * 1024000 + gd * 1600 + gh * 40 + ww];
            }
            __syncthreads();

            #pragma unroll 1
            for (int ci = 0; ci < 4; ++ci) {
                const u64* wci = (const u64*)&sw[(((kt * 8 + cib * 4 + ci) * 27)) * 8];
                #pragma unroll 1
                for (int kd = 0; kd < 3; ++kd) {
                    const float* xb = &sx[((ci * 6 + dl + kd) * 6 + hl) * 44 + w0];
                    const u64* wb  = wci + kd * 36;  // 9 taps x 4 pairs per kd
                    #pragma unroll
                    for (int kh = 0; kh < 3; ++kh) {
                        const float* xr = xb + kh * 44;
                        float4 xa = *(const float4*)(xr);
                        float4 xbv = *(const float4*)(xr + 4);
                        float2 xc = *(const float2*)(xr + 8);
                        u64 xx[10];
                        xx[0] = pack2(xa.x, xa.x);  xx[1] = pack2(xa.y, xa.y);
                        xx[2] = pack2(xa.z, xa.z);  xx[3] = pack2(xa.w, xa.w);
                        xx[4] = pack2(xbv.x, xbv.x); xx[5] = pack2(xbv.y, xbv.y);
                        xx[6] = pack2(xbv.z, xbv.z); xx[7] = pack2(xbv.w, xbv.w);
                        xx[8] = pack2(xc.x, xc.x);  xx[9] = pack2(xc.y, xc.y);
                        #pragma unroll
                        for (int kw = 0; kw < 3; ++kw) {
                            const u64* wp = wb + (kh * 3 + kw) * 4;
                            #pragma unroll
                            for (int cp = 0; cp < 4; ++cp) {
                                u64 wv = wp[cp];
                                #pragma unroll
                                for (int wi = 0; wi < 8; ++wi)
                                    acc[cp][wi] = ffma2(xx[wi + kw], wv, acc[cp][wi]);
                            }
                        }
                    }
                }
            }
        }
    }

    // --- epilogue: unpack pairs, store 2x float4 per co ---
    const int obase = ((b * 32 + cog * 8) * 16 + t) * 64000
                    + (d0 + dl) * 1600 + (h0 + hl) * 40 + w0;
    #pragma unroll
    for (int cp = 0; cp < 4; ++cp) {
        float lo[8], hi[8];
        #pragma unroll
        for (int wi = 0; wi < 8; ++wi) unpack2(lo[wi], hi[wi], acc[cp][wi]);
        float* o0 = out + obase + (cp * 2) * 1024000;
        float* o1 = o0 + 1024000;
        *reinterpret_cast<float4*>(o0)     = make_float4(lo[0], lo[1], lo[2], lo[3]);
        *reinterpret_cast<float4*>(o0 + 4) = make_float4(lo[4], lo[5], lo[6], lo[7]);
        *reinterpret_cast<float4*>(o1)     = make_float4(hi[0], hi[1], hi[2], hi[3]);
        *reinterpret_cast<float4*>(o1 + 4) = make_float4(hi[4], hi[5], hi[6], hi[7]);
    }
}

extern "C" void kernel_launch(void* const* d_in, const int* in_sizes, int n_in,
                              void* d_out, int out_size) {
    const float* x = nullptr; const float* w = nullptr; const float* bias = nullptr;
    for (int i = 0; i < n_in; ++i) {
        if (in_sizes[i] == 16384000)    x    = (const float*)d_in[i];
        else if (in_sizes[i] == 20736)  w    = (const float*)d_in[i];
        else if (in_sizes[i] == 96)     bias = (const float*)d_in[i];
    }
    float* out = (float*)d_out;
    dim3 grid(100, 4, 32);
    conv4d_kernel<<<grid, NT>>>(x, w, bias, out);
}

// round 3
// speedup vs baseline: 1.3529x; 1.3529x over previous
#include <cuda_runtime.h>

// Conv4d via f32x2-packed direct conv.
// x(2,8,16,40,40,40) * W(3,32,8,3,3,3) + bias(3,32) -> out(2,32,16,40,40,40)
// Block: 160 thr (5 warps), tile 8d x 4h x 40w at fixed (b,t,co-group-of-8).
// Thread: 4 co-pairs (8 co) x 8 w = 32 u64 accumulators.
// Phases: kt (valid) x 4 ci-pairs; x slab staged per phase (2ci x 10d x 6h x 44w).

typedef unsigned long long u64;

__device__ __forceinline__ u64 pack2(float lo, float hi) {
    u64 r; asm("mov.b64 %0, {%1, %2};" : "=l"(r) : "f"(lo), "f"(hi)); return r;
}
__device__ __forceinline__ void unpack2(float& lo, float& hi, u64 v) {
    asm("mov.b64 {%0, %1}, %2;" : "=f"(lo), "=f"(hi) : "l"(v));
}
__device__ __forceinline__ u64 ffma2(u64 a, u64 b, u64 c) {
    u64 d; asm("fma.rn.f32x2 %0, %1, %2, %3;" : "=l"(d) : "l"(a), "l"(b), "l"(c)); return d;
}

#define NT 160

__global__ void __launch_bounds__(NT) conv4d_kernel(
    const float* __restrict__ x, const float* __restrict__ weight,
    const float* __restrict__ bias, float* __restrict__ out)
{
    __shared__ __align__(16) float sx[2 * 10 * 6 * 44];   // [ci2][dd10][hh6][ww44] 5280 f
    __shared__ __align__(16) float sw[3 * 8 * 27 * 8];    // [kt][ci8][kd][kh][kw][co8] 5184 f

    const int tid = threadIdx.x;
    const int wg  = tid % 5;            // w0 = wg*8
    const int hl  = (tid / 5) % 4;      // 0..3
    const int dl  = tid / 20;           // 0..7
    const int w0  = wg * 8;

    const int bx  = blockIdx.x;         // 0..49 -> (d0,h0)
    const int cog = blockIdx.y;         // 0..3
    const int bz  = blockIdx.z;         // 0..31 -> (b,t)
    const int d0  = (bx % 5) * 8;
    const int h0  = (bx / 5) * 4;
    const int b   = bz >> 4;
    const int t   = bz & 15;

    // one-time zero of x slab (halo & invalid cells stay zero across phases:
    // the invalid set is fixed for the block)
    for (int idx = tid; idx < 2 * 10 * 6 * 44; idx += NT) sx[idx] = 0.f;

    // one-time weight stage: [kt][ci8][kd][kh][kw][co8]
    for (int idx = tid; idx < 5184; idx += NT) {
        int co = idx & 7;
        int r  = idx >> 3;
        int kw = r % 3; r /= 3;
        int kh = r % 3; r /= 3;
        int kd = r % 3; r /= 3;
        int ci = r & 7;
        int kt = r >> 3;
        sw[idx] = weight[(kt * 32 + cog * 8 + co) * 216 + ci * 27 + kd * 9 + kh * 3 + kw];
    }

    // accumulators init with effective bias
    u64 acc[4][8];
    #pragma unroll
    for (int cp = 0; cp < 4; ++cp) {
        float s0 = 0.f, s1 = 0.f;
        #pragma unroll
        for (int kt = 0; kt < 3; ++kt) {
            int tf = t + kt - 1;
            if (tf >= 0 && tf < 16) {
                s0 += bias[kt * 32 + cog * 8 + cp * 2];
                s1 += bias[kt * 32 + cog * 8 + cp * 2 + 1];
            }
        }
        u64 sv = pack2(s0, s1);
        #pragma unroll
        for (int wi = 0; wi < 8; ++wi) acc[cp][wi] = sv;
    }

    for (int kt = 0; kt < 3; ++kt) {
        const int tf = t + kt - 1;
        if (tf < 0 || tf >= 16) continue;               // uniform across block
        const float* xg = x + b * 8192000 + tf * 64000;

        #pragma unroll 1
        for (int cib = 0; cib < 4; ++cib) {             // ci pairs
            __syncthreads();
            // stage 2 ci x 10 dd x 6 hh x 40 ww interior (4800 elems)
            for (int idx = tid; idx < 4800; idx += NT) {
                int ci = idx / 2400;
                int r  = idx - ci * 2400;
                int dd = r / 240;
                int r2 = r - dd * 240;
                int hh = r2 / 40;
                int ww = r2 - hh * 40;
                int gd = d0 + dd - 1, gh = h0 + hh - 1;
                if ((unsigned)gd < 40u && (unsigned)gh < 40u)
                    sx[((ci * 10 + dd) * 6 + hh) * 44 + ww + 1] =
                        xg[(cib * 2 + ci) * 1024000 + gd * 1600 + gh * 40 + ww];
            }
            __syncthreads();

            #pragma unroll
            for (int ci = 0; ci < 2; ++ci) {
                const u64* wci = (const u64*)sw + (kt * 8 + cib * 2 + ci) * 27 * 4;
                #pragma unroll 1
                for (int kd = 0; kd < 3; ++kd) {
                    const float* xb = &sx[((ci * 10 + dl + kd) * 6 + hl) * 44 + w0];
                    const u64* wb  = wci + kd * 36;
                    #pragma unroll
                    for (int kh = 0; kh < 3; ++kh) {
                        const float* xr = xb + kh * 44;
                        float4 xa  = *(const float4*)(xr);
                        float4 xbv = *(const float4*)(xr + 4);
                        float2 xc  = *(const float2*)(xr + 8);
                        u64 xx[10];
                        xx[0] = pack2(xa.x, xa.x);   xx[1] = pack2(xa.y, xa.y);
                        xx[2] = pack2(xa.z, xa.z);   xx[3] = pack2(xa.w, xa.w);
                        xx[4] = pack2(xbv.x, xbv.x); xx[5] = pack2(xbv.y, xbv.y);
                        xx[6] = pack2(xbv.z, xbv.z); xx[7] = pack2(xbv.w, xbv.w);
                        xx[8] = pack2(xc.x, xc.x);   xx[9] = pack2(xc.y, xc.y);
                        #pragma unroll
                        for (int kw = 0; kw < 3; ++kw) {
                            const u64* wp = wb + (kh * 3 + kw) * 4;
                            #pragma unroll
                            for (int cp = 0; cp < 4; ++cp) {
                                u64 wv = wp[cp];
                                #pragma unroll
                                for (int wi = 0; wi < 8; ++wi)
                                    acc[cp][wi] = ffma2(xx[wi + kw], wv, acc[cp][wi]);
                            }
                        }
                    }
                }
            }
        }
    }

    // epilogue
    const int obase = ((b * 32 + cog * 8) * 16 + t) * 64000
                    + (d0 + dl) * 1600 + (h0 + hl) * 40 + w0;
    #pragma unroll
    for (int cp = 0; cp < 4; ++cp) {
        float lo[8], hi[8];
        #pragma unroll
        for (int wi = 0; wi < 8; ++wi) unpack2(lo[wi], hi[wi], acc[cp][wi]);
        float* o0 = out + obase + (cp * 2) * 1024000;
        float* o1 = o0 + 1024000;
        *reinterpret_cast<float4*>(o0)     = make_float4(lo[0], lo[1], lo[2], lo[3]);
        *reinterpret_cast<float4*>(o0 + 4) = make_float4(lo[4], lo[5], lo[6], lo[7]);
        *reinterpret_cast<float4*>(o1)     = make_float4(hi[0], hi[1], hi[2], hi[3]);
        *reinterpret_cast<float4*>(o1 + 4) = make_float4(hi[4], hi[5], hi[6], hi[7]);
    }
}

extern "C" void kernel_launch(void* const* d_in, const int* in_sizes, int n_in,
                              void* d_out, int out_size) {
    const float* x = nullptr; const float* w = nullptr; const float* bias = nullptr;
    for (int i = 0; i < n_in; ++i) {
        if (in_sizes[i] == 16384000)    x    = (const float*)d_in[i];
        else if (in_sizes[i] == 20736)  w    = (const float*)d_in[i];
        else if (in_sizes[i] == 96)     bias = (const float*)d_in[i];
    }
    float* out = (float*)d_out;
    dim3 grid(50, 4, 32);
    conv4d_kernel<<<grid, NT>>>(x, w, bias, out);
}

// round 4
// speedup vs baseline: 1.4877x; 1.0996x over previous
#include <cuda_runtime.h>

// Conv4d via f32x2 FFMA2 with duplicated-x smem (no register packing).
// x(2,8,16,40,40,40) * W(3,32,8,3,3,3) + bias(3,32) -> out(2,32,16,40,40,40)
// Block: 160 thr, tile 4d x 8h x 40w at fixed (b,t,co-group-of-8).
// Thread: 4 co-pairs x 8 w = 32 u64 accs. Phase = (kt, ci): stage 1 ci slab dup'd.

typedef unsigned long long u64;

__device__ __forceinline__ u64 pack2(float lo, float hi) {
    u64 r; asm("mov.b64 %0, {%1, %2};" : "=l"(r) : "f"(lo), "f"(hi)); return r;
}
__device__ __forceinline__ void unpack2(float& lo, float& hi, u64 v) {
    asm("mov.b64 {%0, %1}, %2;" : "=f"(lo), "=f"(hi) : "l"(v));
}
__device__ __forceinline__ u64 ffma2(u64 a, u64 b, u64 c) {
    u64 d; asm("fma.rn.f32x2 %0, %1, %2, %3;" : "=l"(d) : "l"(a), "l"(b), "l"(c)); return d;
}

#define NT 160

__global__ void __launch_bounds__(NT, 4) conv4d_kernel(
    const float* __restrict__ x, const float* __restrict__ weight,
    const float* __restrict__ bias, float* __restrict__ out)
{
    // dup'd x slab: [dd6][hh10][pair46], each pair = (v,v). 2760 u64 = 22.1 KB
    __shared__ __align__(16) u64 sxd[6 * 10 * 46];
    // weights: [kt][ci8][kd][kh][kw][co8] floats = [..][cp4] u64 pairs. 20.7 KB
    __shared__ __align__(16) float sw[3 * 8 * 27 * 8];

    const int tid = threadIdx.x;
    const int hl  = tid & 7;            // 0..7  (fast: conflict-free LDS.128 rows)
    const int dl  = (tid >> 3) & 3;     // 0..3
    const int wg  = tid >> 5;           // 0..4 -> w0 = wg*8
    const int w0  = wg * 8;

    const int bx  = blockIdx.x;         // 0..49 -> (d0,h0)
    const int cog = blockIdx.y;         // 0..3
    const int bz  = blockIdx.z;         // 0..31 -> (b,t)
    const int d0  = (bx % 10) * 4;
    const int h0  = (bx / 10) * 8;
    const int b   = bz >> 4;
    const int t   = bz & 15;

    // one-time zero (invalid halo cells are block-invariant across phases)
    for (int idx = tid; idx < 6 * 10 * 46; idx += NT) sxd[idx] = 0ull;

    // one-time weight stage: [kt][ci][kd][kh][kw][co8]
    for (int idx = tid; idx < 5184; idx += NT) {
        int co = idx & 7;
        int r  = idx >> 3;
        int kw = r % 3; r /= 3;
        int kh = r % 3; r /= 3;
        int kd = r % 3; r /= 3;
        int ci = r & 7;
        int kt = r >> 3;
        sw[idx] = weight[(kt * 32 + cog * 8 + co) * 216 + ci * 27 + kd * 9 + kh * 3 + kw];
    }

    // accumulators init with effective bias
    u64 acc[4][8];
    #pragma unroll
    for (int cp = 0; cp < 4; ++cp) {
        float s0 = 0.f, s1 = 0.f;
        #pragma unroll
        for (int kt = 0; kt < 3; ++kt) {
            int tf = t + kt - 1;
            if (tf >= 0 && tf < 16) {
                s0 += bias[kt * 32 + cog * 8 + cp * 2];
                s1 += bias[kt * 32 + cog * 8 + cp * 2 + 1];
            }
        }
        u64 sv = pack2(s0, s1);
        #pragma unroll
        for (int wi = 0; wi < 8; ++wi) acc[cp][wi] = sv;
    }

    const int sww = tid % 40;           // staging: w column owned by this thread
    const int sr0 = tid / 40;           // staging: starting row (0..3)

    for (int kt = 0; kt < 3; ++kt) {
        const int tf = t + kt - 1;
        if (tf < 0 || tf >= 16) continue;               // uniform across block
        const float* xg = x + b * 8192000 + tf * 64000;

        #pragma unroll 1
        for (int ci = 0; ci < 8; ++ci) {
            const float* xgc = xg + ci * 1024000;
            __syncthreads();
            // stage slab: 6 dd x 10 hh x 40 ww, write dup pairs
            #pragma unroll 1
            for (int r = 0; r < 15; ++r) {
                int row = sr0 + r * 4;                  // 0..59
                int dd = row / 10, hh = row - dd * 10;
                int gd = d0 + dd - 1, gh = h0 + hh - 1;
                if ((unsigned)gd < 40u && (unsigned)gh < 40u) {
                    float v = xgc[gd * 1600 + gh * 40 + sww];
                    sxd[row * 46 + sww + 1] = pack2(v, v);
                }
            }
            __syncthreads();

            const u64* wci = (const u64*)sw + (kt * 8 + ci) * 27 * 4;
            #pragma unroll 1
            for (int kd = 0; kd < 3; ++kd) {
                #pragma unroll
                for (int kh = 0; kh < 3; ++kh) {
                    const u64* xp = &sxd[((dl + kd) * 10 + hl + kh) * 46 + w0];
                    u64 xx[10];
                    #pragma unroll
                    for (int j = 0; j < 10; ++j) xx[j] = xp[j];   // 5x LDS.128
                    #pragma unroll
                    for (int kw = 0; kw < 3; ++kw) {
                        const u64* wp = wci + (kd * 9 + kh * 3 + kw) * 4;
                        u64 wv0 = wp[0], wv1 = wp[1], wv2 = wp[2], wv3 = wp[3];
                        #pragma unroll
                        for (int wi = 0; wi < 8; ++wi) {
                            acc[0][wi] = ffma2(xx[wi + kw], wv0, acc[0][wi]);
                            acc[1][wi] = ffma2(xx[wi + kw], wv1, acc[1][wi]);
                            acc[2][wi] = ffma2(xx[wi + kw], wv2, acc[2][wi]);
                            acc[3][wi] = ffma2(xx[wi + kw], wv3, acc[3][wi]);
                        }
                    }
                }
            }
        }
    }

    // epilogue
    const int obase = ((b * 32 + cog * 8) * 16 + t) * 64000
                    + (d0 + dl) * 1600 + (h0 + hl) * 40 + w0;
    #pragma unroll
    for (int cp = 0; cp < 4; ++cp) {
        float lo[8], hi[8];
        #pragma unroll
        for (int wi = 0; wi < 8; ++wi) unpack2(lo[wi], hi[wi], acc[cp][wi]);
        float* o0 = out + obase + (cp * 2) * 1024000;
        float* o1 = o0 + 1024000;
        *reinterpret_cast<float4*>(o0)     = make_float4(lo[0], lo[1], lo[2], lo[3]);
        *reinterpret_cast<float4*>(o0 + 4) = make_float4(lo[4], lo[5], lo[6], lo[7]);
        *reinterpret_cast<float4*>(o1)     = make_float4(hi[0], hi[1], hi[2], hi[3]);
        *reinterpret_cast<float4*>(o1 + 4) = make_float4(hi[4], hi[5], hi[6], hi[7]);
    }
}

extern "C" void kernel_launch(void* const* d_in, const int* in_sizes, int n_in,
                              void* d_out, int out_size) {
    const float* x = nullptr; const float* w = nullptr; const float* bias = nullptr;
    for (int i = 0; i < n_in; ++i) {
        if (in_sizes[i] == 16384000)    x    = (const float*)d_in[i];
        else if (in_sizes[i] == 20736)  w    = (const float*)d_in[i];
        else if (in_sizes[i] == 96)     bias = (const float*)d_in[i];
    }
    float* out = (float*)d_out;
    dim3 grid(50, 4, 32);
    conv4d_kernel<<<grid, NT>>>(x, w, bias, out);
}